// round 3
// baseline (speedup 1.0000x reference)
#include <cuda_runtime.h>
#include <cuda_fp16.h>
#include <math.h>

#define T_DIM 2048
#define B_DIM 1024
#define A_DIM 4
#define D_DIM 128
#define P_DIM 256
#define TC    32
#define NCH   (T_DIM / TC)
#define LDW   68            // Hs row stride in 32-bit words (136 halves, pad 8)
#define LDQ   36            // Qs row stride in half2 (72 halves: 64 + pad 8)
#define NLOGIT (T_DIM * B_DIM * A_DIM)

// scratch: per (b,t,a): (s = r*a, a)
__device__ float2 g_SA[(size_t)B_DIM * T_DIM * A_DIM];

static __device__ __forceinline__ float nan0(float x) { return (x == x) ? x : 0.0f; }
static __device__ __forceinline__ float clipf(float x, float lo, float hi) {
    return fminf(fmaxf(x, lo), hi);
}
static __device__ __forceinline__ unsigned smem_u32(const void* p) {
    return (unsigned)__cvta_generic_to_shared(p);
}

// ---------------------------------------------------------------------------
// Zero the logits region of out (atomics accumulate into it)
// ---------------------------------------------------------------------------
__global__ void zero_kernel(float4* __restrict__ out4) {
    int gid = blockIdx.x * blockDim.x + threadIdx.x;
    if (gid < NLOGIT / 4) out4[gid] = make_float4(0.f, 0.f, 0.f, 0.f);
}

// ---------------------------------------------------------------------------
// Prep: inputs (T,B,1,9) -> g_SA[b][t][a] = (reward*action, action)
// ---------------------------------------------------------------------------
__global__ void prep_kernel(const float* __restrict__ inp) {
    int gid = blockIdx.x * blockDim.x + threadIdx.x;
    if (gid >= T_DIM * B_DIM) return;
    int b = gid % B_DIM;
    int t = gid / B_DIM;
    const float* row = inp + ((size_t)t * B_DIM + b) * 9;
    float2* o = g_SA + ((size_t)b * T_DIM + t) * A_DIM;
#pragma unroll
    for (int a = 0; a < A_DIM; a++) {
        float act = nan0(row[a]);
        float r   = nan0(row[4 + a]);
        o[a] = make_float2(r * act, act);
    }
}

// mma.sync m16n8k16 row.col f16 -> f32
static __device__ __forceinline__ void mma16816(float* acc, const unsigned* a,
                                                unsigned b0, unsigned b1) {
    asm volatile(
        "mma.sync.aligned.m16n8k16.row.col.f32.f16.f16.f32 "
        "{%0,%1,%2,%3}, {%4,%5,%6,%7}, {%8,%9}, {%0,%1,%2,%3};\n"
        : "+f"(acc[0]), "+f"(acc[1]), "+f"(acc[2]), "+f"(acc[3])
        : "r"(a[0]), "r"(a[1]), "r"(a[2]), "r"(a[3]), "r"(b0), "r"(b1));
}

static __device__ __forceinline__ void ldsm4(unsigned* r, unsigned addr) {
    asm volatile(
        "ldmatrix.sync.aligned.m8n8.x4.shared.b16 {%0,%1,%2,%3}, [%4];\n"
        : "=r"(r[0]), "=r"(r[1]), "=r"(r[2]), "=r"(r[3]) : "r"(addr));
}

// ---------------------------------------------------------------------------
// Main: TWO CTAs per b (N-half split). 256 threads (8 warps), 2 CTAs/SM.
// SMEM: sa_s[0,1024) beta[1024,1280) kappa[1280,1536) lpart[1536,3584)
//       Ct[4096,+17408) Hs[21504,+34816) Qs[56320,+18432)  total 74752 B
// ---------------------------------------------------------------------------
#define SMEM_BYTES 74752

__global__ void __launch_bounds__(256, 2) gql_main(
    const float* __restrict__ inp,
    const float* __restrict__ phi_raw,  const float* __restrict__ chi_raw,
    const float* __restrict__ beta_raw, const float* __restrict__ kappa_raw,
    const float* __restrict__ C_raw,    float* __restrict__ out) {
    extern __shared__ char sm[];
    float2*   sa_s    = (float2*)sm;
    float*    beta_s  = (float*)(sm + 1024);
    float*    kappa_s = (float*)(sm + 1280);
    float*    lpart   = (float*)(sm + 1536);
    __half*   Ct      = (__half*)(sm + 4096);
    unsigned* Ct_w    = (unsigned*)Ct;
    __half2*  Hs_h2   = (__half2*)(sm + 21504);
    __half2*  Qs_h2   = (__half2*)(sm + 56320);

    const int b    = blockIdx.x >> 1;
    const int nh   = blockIdx.x & 1;          // which 64-col half of e/d this CTA owns
    const int tid  = threadIdx.x;
    const int lane = tid & 31;
    const int w    = tid >> 5;
    const int g    = lane >> 2;
    const int tg   = lane & 3;
    const int pid  = min(max((int)nan0(__ldg(inp + (size_t)b * 9 + 8)), 0), P_DIM - 1);

    // scan assignment: a = tid>>6, d-pair (d0, d0+1)
    const int aidx = tid >> 6;
    const int d2   = tid & 63;
    const int d0   = d2 * 2;

    float phr0 = phi_raw[pid * D_DIM + d0], phr1 = phi_raw[pid * D_DIM + d0 + 1];
    float chr0 = chi_raw[pid * D_DIM + d0], chr1 = chi_raw[pid * D_DIM + d0 + 1];
    float phi0 = clipf(1.0f / (1.0f + expf(-phr0)), 0.01f, 0.99f);
    float phi1 = clipf(1.0f / (1.0f + expf(-phr1)), 0.01f, 0.99f);
    float chi0 = clipf(1.0f / (1.0f + expf(-chr0)), 0.01f, 0.99f);
    float chi1 = clipf(1.0f / (1.0f + expf(-chr1)), 0.01f, 0.99f);
    float omp0 = 1.0f - phi0, omp1 = 1.0f - phi1;
    float omc0 = 1.0f - chi0, omc1 = 1.0f - chi1;

    // beta/kappa for this CTA's 64-col half
    if (tid < 64) {
        float br = beta_raw[pid * D_DIM + nh * 64 + tid];
        float sp = fmaxf(br, 0.0f) + log1pf(expf(-fabsf(br)));
        beta_s[tid]  = clipf(sp, 0.1f, 10.0f);
        kappa_s[tid] = clipf(kappa_raw[pid * D_DIM + nh * 64 + tid], -10.0f, 10.0f);
    }
    // Ct[e_local][d] = clip(C[d][nh*64 + e_local])
    for (int i = tid; i < 64 * D_DIM; i += 256) {
        int e = i >> 7, d = i & 127;
        float c = clipf(C_raw[(size_t)pid * (D_DIM * D_DIM) + d * D_DIM + nh * 64 + e],
                        -10.0f, 10.0f);
        Ct[e * 136 + d] = __float2half(c);
    }
    __syncthreads();

    // warp tile: rows [mw*64, +64), local cols [nw*16, +16)
    const int mw = w & 1;
    const int nw = w >> 1;

    // B fragments resident across all chunks: 2 n-tiles x 8 k-steps x 2 regs
    unsigned bfr[2][8][2];
#pragma unroll
    for (int nt = 0; nt < 2; nt++) {
        const unsigned* cb = Ct_w + (nw * 16 + nt * 8 + g) * LDW;
#pragma unroll
        for (int ks = 0; ks < 8; ks++) {
            bfr[nt][ks][0] = cb[ks * 8 + tg];
            bfr[nt][ks][1] = cb[ks * 8 + tg + 4];
        }
    }
    float2 bet[2], kap[2];
#pragma unroll
    for (int nt = 0; nt < 2; nt++) {
        int c0 = nw * 16 + nt * 8 + tg * 2;
        bet[nt] = make_float2(beta_s[c0], beta_s[c0 + 1]);
        kap[nt] = make_float2(kappa_s[c0], kappa_s[c0 + 1]);
    }

    // ldmatrix.x4 base addresses per mt (A fragments from Hs)
    unsigned amt[4];
    {
        unsigned hs0 = smem_u32(Hs_h2);
        int r = (lane & 15);
        int cb = (lane & 16) ? 16 : 0;    // +8 halves for k-high tiles
#pragma unroll
        for (int mt = 0; mt < 4; mt++)
            amt[mt] = hs0 + (unsigned)((mw * 64 + mt * 16 + r) * (LDW * 4) + cb);
    }

    // Q write predicate: this thread's d-pair lies in this CTA's half?
    const bool qwr  = (d2 >> 5) == nh;
    const int  qcol = d2 & 31;

    float q0 = 0.5f, q1 = 0.5f, h0 = 0.0f, h1 = 0.0f;
    const float2* sa_src = g_SA + (size_t)b * T_DIM * A_DIM;

    for (int c = 0; c < NCH; c++) {
        if (tid < 128) sa_s[tid] = sa_src[c * 128 + tid];
        __syncthreads();

        // ---- scan: fp32 state, fp16 tiles ----
#pragma unroll 4
        for (int tt = 0; tt < TC; tt++) {
            float2 sa = sa_s[tt * 4 + aidx];
            float s = sa.x, a = sa.y;
            q0 = omp0 * q0 + phi0 * s;
            q1 = omp1 * q1 + phi1 * s;
            h0 = omc0 * h0 + chi0 * a;
            h1 = omc1 * h1 + chi1 * a;
            int row = tt * 4 + aidx;
            Hs_h2[row * LDW + d2] = __floats2half2_rn(h0, h1);
            if (qwr) Qs_h2[row * LDQ + qcol] = __floats2half2_rn(q0, q1);
        }
        __syncthreads();

        // ---- GEMM: U(128 x 64-half) = H(128x128) x Ct ----
        float acc[4][2][4];
#pragma unroll
        for (int mt = 0; mt < 4; mt++)
#pragma unroll
            for (int nt = 0; nt < 2; nt++)
#pragma unroll
                for (int i = 0; i < 4; i++) acc[mt][nt][i] = 0.0f;

#pragma unroll
        for (int ks = 0; ks < 8; ks++) {
#pragma unroll
            for (int mt = 0; mt < 4; mt++) {
                unsigned af[4];
                ldsm4(af, amt[mt] + ks * 32);
                mma16816(acc[mt][0], af, bfr[0][ks][0], bfr[0][ks][1]);
                mma16816(acc[mt][1], af, bfr[1][ks][0], bfr[1][ks][1]);
            }
        }

        // ---- epilogue: partial logit over this CTA's 64 cols ----
#pragma unroll
        for (int mt = 0; mt < 4; mt++) {
            int r0 = mw * 64 + mt * 16 + g;
            float p0 = 0.0f, p1 = 0.0f;
#pragma unroll
            for (int nt = 0; nt < 2; nt++) {
                int cl = nw * 8 + nt * 4 + tg;            // local half2 col 0..31
                float2 qv0 = __half22float2(Qs_h2[r0 * LDQ + cl]);
                float2 qv1 = __half22float2(Qs_h2[(r0 + 8) * LDQ + cl]);
                float2 hv0 = __half22float2(Hs_h2[r0 * LDW + nh * 32 + cl]);
                float2 hv1 = __half22float2(Hs_h2[(r0 + 8) * LDW + nh * 32 + cl]);
                p0 += (acc[mt][nt][0] + bet[nt].x) * qv0.x
                    + (acc[mt][nt][1] + bet[nt].y) * qv0.y
                    + kap[nt].x * hv0.x + kap[nt].y * hv0.y;
                p1 += (acc[mt][nt][2] + bet[nt].x) * qv1.x
                    + (acc[mt][nt][3] + bet[nt].y) * qv1.y
                    + kap[nt].x * hv1.x + kap[nt].y * hv1.y;
            }
            p0 += __shfl_xor_sync(0xffffffffu, p0, 1);
            p0 += __shfl_xor_sync(0xffffffffu, p0, 2);
            p1 += __shfl_xor_sync(0xffffffffu, p1, 1);
            p1 += __shfl_xor_sync(0xffffffffu, p1, 2);
            if (tg == 0) {
                lpart[nw * 128 + r0]     = p0;
                lpart[nw * 128 + r0 + 8] = p1;
            }
        }
        __syncthreads();

        if (tid < 128) {   // combine 4 warp-column partials, accumulate to out
            float lg = lpart[tid] + lpart[128 + tid] + lpart[256 + tid] + lpart[384 + tid];
            int tt = tid >> 2, a = tid & 3;
            atomicAdd(out + ((size_t)(c * TC + tt) * B_DIM + b) * A_DIM + a, lg);
        }
    }

    // final q, h: shape (B, A, D); only the nh==0 CTA writes (full state held)
    if (nh == 0) {
        float* out_q = out + (size_t)NLOGIT;
        float* out_h = out_q + B_DIM * A_DIM * D_DIM;
        ((float2*)out_q)[(b * A_DIM + aidx) * 64 + d2] = make_float2(q0, q1);
        ((float2*)out_h)[(b * A_DIM + aidx) * 64 + d2] = make_float2(h0, h1);
    }
}

extern "C" void kernel_launch(void* const* d_in, const int* in_sizes, int n_in,
                              void* d_out, int out_size) {
    const float* inp       = (const float*)d_in[0];
    const float* phi_raw   = (const float*)d_in[1];
    const float* chi_raw   = (const float*)d_in[2];
    const float* beta_raw  = (const float*)d_in[3];
    const float* kappa_raw = (const float*)d_in[4];
    const float* C_raw     = (const float*)d_in[5];
    float* out = (float*)d_out;

    cudaFuncSetAttribute(gql_main, cudaFuncAttributeMaxDynamicSharedMemorySize,
                         SMEM_BYTES);

    zero_kernel<<<NLOGIT / 4 / 256, 256>>>((float4*)out);
    prep_kernel<<<(T_DIM * B_DIM + 255) / 256, 256>>>(inp);
    gql_main<<<B_DIM * 2, 256, SMEM_BYTES>>>(inp, phi_raw, chi_raw, beta_raw,
                                             kappa_raw, C_raw, out);
}

// round 4
// speedup vs baseline: 1.3219x; 1.3219x over previous
#include <cuda_runtime.h>
#include <cuda_fp16.h>
#include <math.h>

#define T_DIM 2048
#define B_DIM 1024
#define A_DIM 4
#define D_DIM 128
#define P_DIM 256
#define TC    32
#define NCH   (T_DIM / TC)
#define LDW   68            // tile row stride: 68 words = 136 halves (128 + pad 8)
#define LDB   272           // tile row stride in bytes
#define NLOGIT (T_DIM * B_DIM * A_DIM)

// scratch: per (b,t,a): (s = r*a, a)
__device__ float2 g_SA[(size_t)B_DIM * T_DIM * A_DIM];

static __device__ __forceinline__ float nan0(float x) { return (x == x) ? x : 0.0f; }
static __device__ __forceinline__ float clipf(float x, float lo, float hi) {
    return fminf(fmaxf(x, lo), hi);
}
static __device__ __forceinline__ unsigned smem_u32(const void* p) {
    return (unsigned)__cvta_generic_to_shared(p);
}

// ---------------------------------------------------------------------------
// Prep: inputs (T,B,1,9) -> g_SA[b][t][a] = (reward*action, action)
// ---------------------------------------------------------------------------
__global__ void prep_kernel(const float* __restrict__ inp) {
    int gid = blockIdx.x * blockDim.x + threadIdx.x;
    if (gid >= T_DIM * B_DIM) return;
    int b = gid % B_DIM;
    int t = gid / B_DIM;
    const float* row = inp + ((size_t)t * B_DIM + b) * 9;
    float2* o = g_SA + ((size_t)b * T_DIM + t) * A_DIM;
#pragma unroll
    for (int a = 0; a < A_DIM; a++) {
        float act = nan0(row[a]);
        float r   = nan0(row[4 + a]);
        o[a] = make_float2(r * act, act);
    }
}

// mma.sync m16n8k16 row.col f16 -> f32
static __device__ __forceinline__ void mma16816(float* acc, const unsigned* a,
                                                unsigned b0, unsigned b1) {
    asm volatile(
        "mma.sync.aligned.m16n8k16.row.col.f32.f16.f16.f32 "
        "{%0,%1,%2,%3}, {%4,%5,%6,%7}, {%8,%9}, {%0,%1,%2,%3};\n"
        : "+f"(acc[0]), "+f"(acc[1]), "+f"(acc[2]), "+f"(acc[3])
        : "r"(a[0]), "r"(a[1]), "r"(a[2]), "r"(a[3]), "r"(b0), "r"(b1));
}

static __device__ __forceinline__ void ldsm4(unsigned* r, unsigned addr) {
    asm volatile(
        "ldmatrix.sync.aligned.m8n8.x4.shared.b16 {%0,%1,%2,%3}, [%4];\n"
        : "=r"(r[0]), "=r"(r[1]), "=r"(r[2]), "=r"(r[3]) : "r"(addr));
}

// ---------------------------------------------------------------------------
// Main: ONE CTA per b, 256 threads (8 warps), 2 CTAs/SM (regs<=128).
// Warp tile: 32 rows x 32 cols, two passes over the 128-col N dimension.
// SMEM: sa2[0,2048) beta[2048,2560) kappa[2560,3072) lpart[3072,4096)
//       Ct[4096,+34816) Hs[38912,+34816) Qs[73728,+34816)  total 108544 B
// ---------------------------------------------------------------------------
#define SMEM_BYTES 108544

__global__ void __launch_bounds__(256, 2) gql_main(
    const float* __restrict__ inp,
    const float* __restrict__ phi_raw,  const float* __restrict__ chi_raw,
    const float* __restrict__ beta_raw, const float* __restrict__ kappa_raw,
    const float* __restrict__ C_raw,    float* __restrict__ out) {
    extern __shared__ char sm[];
    float2*   sa_s    = (float2*)sm;                 // double buffer: 2 x 128
    float*    beta_s  = (float*)(sm + 2048);
    float*    kappa_s = (float*)(sm + 2560);
    float*    lpart   = (float*)(sm + 3072);         // 2 x 128
    __half*   Ct      = (__half*)(sm + 4096);
    __half2*  Hs_h2   = (__half2*)(sm + 38912);
    __half2*  Qs_h2   = (__half2*)(sm + 73728);

    const int b    = blockIdx.x;
    const int tid  = threadIdx.x;
    const int lane = tid & 31;
    const int w    = tid >> 5;
    const int g    = lane >> 2;
    const int tg   = lane & 3;
    const int pid  = min(max((int)nan0(__ldg(inp + (size_t)b * 9 + 8)), 0), P_DIM - 1);

    // scan assignment: a = tid>>6, d-pair (d0, d0+1)
    const int aidx = tid >> 6;
    const int d2   = tid & 63;
    const int d0   = d2 * 2;

    float phr0 = phi_raw[pid * D_DIM + d0], phr1 = phi_raw[pid * D_DIM + d0 + 1];
    float chr0 = chi_raw[pid * D_DIM + d0], chr1 = chi_raw[pid * D_DIM + d0 + 1];
    float phi0 = clipf(1.0f / (1.0f + expf(-phr0)), 0.01f, 0.99f);
    float phi1 = clipf(1.0f / (1.0f + expf(-phr1)), 0.01f, 0.99f);
    float chi0 = clipf(1.0f / (1.0f + expf(-chr0)), 0.01f, 0.99f);
    float chi1 = clipf(1.0f / (1.0f + expf(-chr1)), 0.01f, 0.99f);
    float omp0 = 1.0f - phi0, omp1 = 1.0f - phi1;
    float omc0 = 1.0f - chi0, omc1 = 1.0f - chi1;

    if (tid < 128) {
        float br = beta_raw[pid * D_DIM + tid];
        float sp = fmaxf(br, 0.0f) + log1pf(expf(-fabsf(br)));
        beta_s[tid]  = clipf(sp, 0.1f, 10.0f);
        kappa_s[tid] = clipf(kappa_raw[pid * D_DIM + tid], -10.0f, 10.0f);
    }
    // Ct[e][d] = clip(C[d][e])  (col-major B operand)
    for (int i = tid; i < D_DIM * D_DIM; i += 256) {
        int d = i >> 7, e = i & 127;
        Ct[e * 136 + d] = __float2half(clipf(C_raw[(size_t)pid * (D_DIM * D_DIM) + i],
                                             -10.0f, 10.0f));
    }

    // warp tiling: mw = row group (32 rows), nwp = col group (32 of 64 per pass)
    const int mw  = w & 3;
    const int nwp = w >> 2;

    // ldmatrix base addresses
    unsigned amt[2], bb[2];
    {
        unsigned hs0 = smem_u32(Hs_h2);
        int r  = lane & 15;
        int cb = (lane & 16) ? 16 : 0;
#pragma unroll
        for (int mt = 0; mt < 2; mt++)
            amt[mt] = hs0 + (unsigned)((mw * 32 + mt * 16 + r) * LDB + cb);

        unsigned ct0 = smem_u32(Ct);
        int brow = (lane & 7) + ((lane & 16) ? 8 : 0);
        int bcol = (lane & 8) ? 16 : 0;
#pragma unroll
        for (int pr = 0; pr < 2; pr++)
            bb[pr] = ct0 + (unsigned)((nwp * 32 + pr * 16 + brow) * LDB + bcol);
    }

    float q0 = 0.5f, q1 = 0.5f, h0 = 0.0f, h1 = 0.0f;
    const float2* sa_src = g_SA + (size_t)b * T_DIM * A_DIM;

    // preload sa chunk 0 into buffer 0
    if (tid < 128) sa_s[tid] = sa_src[tid];
    __syncthreads();

    for (int c = 0; c < NCH; c++) {
        const int cb = c & 1;
        // prefetch next chunk's sa (LDG in flight under the scan)
        float2 nxt;
        const bool pf = (tid < 128) && (c + 1 < NCH);
        if (pf) nxt = __ldg((const float2*)(sa_src + (c + 1) * 128 + tid));

        // ---- scan: fp32 state, fp16 tiles ----
        const float2* sab = sa_s + cb * 128;
#pragma unroll 4
        for (int tt = 0; tt < TC; tt++) {
            float2 sa = sab[tt * 4 + aidx];
            float s = sa.x, a = sa.y;
            q0 = omp0 * q0 + phi0 * s;
            q1 = omp1 * q1 + phi1 * s;
            h0 = omc0 * h0 + chi0 * a;
            h1 = omc1 * h1 + chi1 * a;
            int row = tt * 4 + aidx;
            Hs_h2[row * LDW + d2] = __floats2half2_rn(h0, h1);
            Qs_h2[row * LDW + d2] = __floats2half2_rn(q0, q1);
        }
        if (pf) sa_s[(cb ^ 1) * 128 + tid] = nxt;
        __syncthreads();   // tiles ready

        // ---- GEMM + epilogue, two passes over N halves ----
        float pl0[2] = {0.f, 0.f}, pl1[2] = {0.f, 0.f};
#pragma unroll
        for (int p = 0; p < 2; p++) {
            float acc[2][4][4];
#pragma unroll
            for (int mt = 0; mt < 2; mt++)
#pragma unroll
                for (int nt = 0; nt < 4; nt++)
#pragma unroll
                    for (int i = 0; i < 4; i++) acc[mt][nt][i] = 0.0f;

#pragma unroll
            for (int ks = 0; ks < 8; ks++) {
                unsigned bf0[4], bf1[4];
                ldsm4(bf0, bb[0] + p * (64 * LDB) + ks * 32);
                ldsm4(bf1, bb[1] + p * (64 * LDB) + ks * 32);
#pragma unroll
                for (int mt = 0; mt < 2; mt++) {
                    unsigned af[4];
                    ldsm4(af, amt[mt] + ks * 32);
                    mma16816(acc[mt][0], af, bf0[0], bf0[1]);
                    mma16816(acc[mt][1], af, bf0[2], bf0[3]);
                    mma16816(acc[mt][2], af, bf1[0], bf1[1]);
                    mma16816(acc[mt][3], af, bf1[2], bf1[3]);
                }
            }

            // epilogue for this pass: cols p*64 + nwp*32 + nt*8 + tg*2
#pragma unroll
            for (int nt = 0; nt < 4; nt++) {
                int col = p * 64 + nwp * 32 + nt * 8 + tg * 2;
                float2 bet = *(const float2*)(beta_s + col);
                float2 kap = *(const float2*)(kappa_s + col);
                int cw = col >> 1;
#pragma unroll
                for (int mt = 0; mt < 2; mt++) {
                    int r0 = mw * 32 + mt * 16 + g;
                    float2 qv0 = __half22float2(Qs_h2[r0 * LDW + cw]);
                    float2 qv1 = __half22float2(Qs_h2[(r0 + 8) * LDW + cw]);
                    float2 hv0 = __half22float2(Hs_h2[r0 * LDW + cw]);
                    float2 hv1 = __half22float2(Hs_h2[(r0 + 8) * LDW + cw]);
                    pl0[mt] += (acc[mt][nt][0] + bet.x) * qv0.x
                             + (acc[mt][nt][1] + bet.y) * qv0.y
                             + kap.x * hv0.x + kap.y * hv0.y;
                    pl1[mt] += (acc[mt][nt][2] + bet.x) * qv1.x
                             + (acc[mt][nt][3] + bet.y) * qv1.y
                             + kap.x * hv1.x + kap.y * hv1.y;
                }
            }
        }

        // reduce over tg (8 cols each -> 64 cols of this warp's n-group)
#pragma unroll
        for (int mt = 0; mt < 2; mt++) {
            pl0[mt] += __shfl_xor_sync(0xffffffffu, pl0[mt], 1);
            pl0[mt] += __shfl_xor_sync(0xffffffffu, pl0[mt], 2);
            pl1[mt] += __shfl_xor_sync(0xffffffffu, pl1[mt], 1);
            pl1[mt] += __shfl_xor_sync(0xffffffffu, pl1[mt], 2);
            if (tg == 0) {
                int r0 = mw * 32 + mt * 16 + g;
                lpart[nwp * 128 + r0]     = pl0[mt];
                lpart[nwp * 128 + r0 + 8] = pl1[mt];
            }
        }
        __syncthreads();   // lpart ready; also protects tiles & sa buffers

        if (tid < 128) {   // combine 2 n-group partials, store logits
            float lg = lpart[tid] + lpart[128 + tid];
            int tt = tid >> 2, a = tid & 3;
            out[((size_t)(c * TC + tt) * B_DIM + b) * A_DIM + a] = lg;
        }
    }

    // final q, h: shape (B, A, D)
    float* out_q = out + (size_t)NLOGIT;
    float* out_h = out_q + B_DIM * A_DIM * D_DIM;
    ((float2*)out_q)[(b * A_DIM + aidx) * 64 + d2] = make_float2(q0, q1);
    ((float2*)out_h)[(b * A_DIM + aidx) * 64 + d2] = make_float2(h0, h1);
}

extern "C" void kernel_launch(void* const* d_in, const int* in_sizes, int n_in,
                              void* d_out, int out_size) {
    const float* inp       = (const float*)d_in[0];
    const float* phi_raw   = (const float*)d_in[1];
    const float* chi_raw   = (const float*)d_in[2];
    const float* beta_raw  = (const float*)d_in[3];
    const float* kappa_raw = (const float*)d_in[4];
    const float* C_raw     = (const float*)d_in[5];
    float* out = (float*)d_out;

    cudaFuncSetAttribute(gql_main, cudaFuncAttributeMaxDynamicSharedMemorySize,
                         SMEM_BYTES);

    prep_kernel<<<(T_DIM * B_DIM + 255) / 256, 256>>>(inp);
    gql_main<<<B_DIM, 256, SMEM_BYTES>>>(inp, phi_raw, chi_raw, beta_raw,
                                         kappa_raw, C_raw, out);
}

// round 6
// speedup vs baseline: 1.4542x; 1.1001x over previous
#include <cuda_runtime.h>
#include <cuda_fp16.h>
#include <math.h>

#define T_DIM 2048
#define B_DIM 1024
#define A_DIM 4
#define D_DIM 128
#define P_DIM 256
#define TC    32
#define NCH   (T_DIM / TC)
#define LDW   68            // tile row stride: 68 words = 136 halves (128 + pad 8)
#define LDB   272           // tile row stride in bytes
#define NLOGIT (T_DIM * B_DIM * A_DIM)

// SMEM layout (bytes)
#define OFF_SA    0          // 2 x 128 float2            [0,2048)
#define OFF_BETA  2048       // 128 floats                [2048,2560)
#define OFF_LPART 3072       // 2 x 128 floats            [3072,4096)
#define OFF_CT    4096       // 136 rows x 272 B = 36992  [4096,41088)
#define OFF_HS    41088      // 128 rows x 272 B = 34816  [41088,75904)
#define OFF_QS    75904      // 128 rows x 272 B = 34816  [75904,110720)
#define SMEM_BYTES 110720

// scratch: per (b,t,a): (s = r*a, a)
__device__ float2 g_SA[(size_t)B_DIM * T_DIM * A_DIM];

static __device__ __forceinline__ float nan0(float x) { return (x == x) ? x : 0.0f; }
static __device__ __forceinline__ float clipf(float x, float lo, float hi) {
    return fminf(fmaxf(x, lo), hi);
}
static __device__ __forceinline__ unsigned smem_u32(const void* p) {
    return (unsigned)__cvta_generic_to_shared(p);
}

__global__ void prep_kernel(const float* __restrict__ inp) {
    int gid = blockIdx.x * blockDim.x + threadIdx.x;
    if (gid >= T_DIM * B_DIM) return;
    int b = gid % B_DIM;
    int t = gid / B_DIM;
    const float* row = inp + ((size_t)t * B_DIM + b) * 9;
    float2* o = g_SA + ((size_t)b * T_DIM + t) * A_DIM;
#pragma unroll
    for (int a = 0; a < A_DIM; a++) {
        float act = nan0(row[a]);
        float r   = nan0(row[4 + a]);
        o[a] = make_float2(r * act, act);
    }
}

// mma.sync m16n8k16 row.col f16 -> f32
static __device__ __forceinline__ void mma16816(float* acc, const unsigned* a,
                                                unsigned b0, unsigned b1) {
    asm volatile(
        "mma.sync.aligned.m16n8k16.row.col.f32.f16.f16.f32 "
        "{%0,%1,%2,%3}, {%4,%5,%6,%7}, {%8,%9}, {%0,%1,%2,%3};\n"
        : "+f"(acc[0]), "+f"(acc[1]), "+f"(acc[2]), "+f"(acc[3])
        : "r"(a[0]), "r"(a[1]), "r"(a[2]), "r"(a[3]), "r"(b0), "r"(b1));
}
static __device__ __forceinline__ void ldsm4(unsigned* r, unsigned addr) {
    asm volatile(
        "ldmatrix.sync.aligned.m8n8.x4.shared.b16 {%0,%1,%2,%3}, [%4];\n"
        : "=r"(r[0]), "=r"(r[1]), "=r"(r[2]), "=r"(r[3]) : "r"(addr));
}
static __device__ __forceinline__ void ldsm2(unsigned* r, unsigned addr) {
    asm volatile(
        "ldmatrix.sync.aligned.m8n8.x2.shared.b16 {%0,%1}, [%2];\n"
        : "=r"(r[0]), "=r"(r[1]) : "r"(addr));
}

// ---------------------------------------------------------------------------
// Main: ONE CTA per b, 256 threads (8 warps), 2 CTAs/SM.
// GEMM: U(128 x 136) = H(128x128) x Ct^T; Ct rows 0-127 = C cols, row 128 = kappa
// => U[:,128] = kappa . h  (kappa-term folded into tensor pipe).
// Epilogue: Q fragments via ldmatrix (acc-layout-compatible), beta via FADD.
// ---------------------------------------------------------------------------
__global__ void __launch_bounds__(256, 2) gql_main(
    const float* __restrict__ inp,
    const float* __restrict__ phi_raw,  const float* __restrict__ chi_raw,
    const float* __restrict__ beta_raw, const float* __restrict__ kappa_raw,
    const float* __restrict__ C_raw,    float* __restrict__ out) {
    extern __shared__ char sm[];
    float2*   sa_s    = (float2*)(sm + OFF_SA);
    float*    beta_s  = (float*)(sm + OFF_BETA);
    float*    lpart   = (float*)(sm + OFF_LPART);
    __half*   Ct      = (__half*)(sm + OFF_CT);
    __half2*  Hs_h2   = (__half2*)(sm + OFF_HS);
    __half2*  Qs_h2   = (__half2*)(sm + OFF_QS);

    const int b    = blockIdx.x;
    const int tid  = threadIdx.x;
    const int lane = tid & 31;
    const int w    = tid >> 5;
    const int g    = lane >> 2;
    const int tg   = lane & 3;
    const int pid  = min(max((int)nan0(__ldg(inp + (size_t)b * 9 + 8)), 0), P_DIM - 1);

    // scan assignment: a = tid>>6, d-pair (d0, d0+1)
    const int aidx = tid >> 6;
    const int d2   = tid & 63;
    const int d0   = d2 * 2;

    float phr0 = phi_raw[pid * D_DIM + d0], phr1 = phi_raw[pid * D_DIM + d0 + 1];
    float chr0 = chi_raw[pid * D_DIM + d0], chr1 = chi_raw[pid * D_DIM + d0 + 1];
    float phi0 = clipf(1.0f / (1.0f + expf(-phr0)), 0.01f, 0.99f);
    float phi1 = clipf(1.0f / (1.0f + expf(-phr1)), 0.01f, 0.99f);
    float chi0 = clipf(1.0f / (1.0f + expf(-chr0)), 0.01f, 0.99f);
    float chi1 = clipf(1.0f / (1.0f + expf(-chr1)), 0.01f, 0.99f);
    float omp0 = 1.0f - phi0, omp1 = 1.0f - phi1;
    float omc0 = 1.0f - chi0, omc1 = 1.0f - chi1;

    // zero Ct rows 128..135 (extra N-tile; only row 128 becomes kappa)
    for (int i = tid; i < 8 * LDW; i += 256)
        ((unsigned*)(sm + OFF_CT + 128 * LDB))[i] = 0;
    if (tid < 128) {
        float br = beta_raw[pid * D_DIM + tid];
        float sp = fmaxf(br, 0.0f) + log1pf(expf(-fabsf(br)));
        beta_s[tid] = clipf(sp, 0.1f, 10.0f);
        // Ct row 128 = kappa
        Ct[128 * 136 + tid] =
            __float2half(clipf(kappa_raw[pid * D_DIM + tid], -10.0f, 10.0f));
    }
    // Ct[e][d] = clip(C[d][e])  (col-major B operand)
    for (int i = tid; i < D_DIM * D_DIM; i += 256) {
        int d = i >> 7, e = i & 127;
        Ct[e * 136 + d] = __float2half(clipf(C_raw[(size_t)pid * (D_DIM * D_DIM) + i],
                                             -10.0f, 10.0f));
    }

    // warp tiling: mw = row group (32 rows), nwp = col group (32 of 64 per pass)
    const int mw  = w & 3;
    const int nwp = w >> 2;

    // ldmatrix base addresses
    unsigned amt[2], bb[2], bbx, qbase;
    {
        unsigned hs0 = smem_u32(Hs_h2);
        int r  = lane & 15;
        int cb = (lane & 16) ? 16 : 0;
#pragma unroll
        for (int mt = 0; mt < 2; mt++)
            amt[mt] = hs0 + (unsigned)((mw * 32 + mt * 16 + r) * LDB + cb);

        unsigned ct0 = smem_u32(Ct);
        int brow = (lane & 7) + ((lane & 16) ? 8 : 0);
        int bcol = (lane & 8) ? 16 : 0;
#pragma unroll
        for (int pr = 0; pr < 2; pr++)
            bb[pr] = ct0 + (unsigned)((nwp * 32 + pr * 16 + brow) * LDB + bcol);
        // extra kappa-tile: rows e=128..135 (x2: lanes 0-15 matter)
        bbx = ct0 + (unsigned)((128 + (lane & 7)) * LDB + ((lane & 8) ? 16 : 0));

        qbase = smem_u32(Qs_h2) + (unsigned)((mw * 32 + lane) * LDB);
    }

    float q0 = 0.5f, q1 = 0.5f, h0 = 0.0f, h1 = 0.0f;
    const float2* sa_src = g_SA + (size_t)b * T_DIM * A_DIM;

    // preload sa chunk 0
    if (tid < 128) sa_s[tid] = sa_src[tid];
    __syncthreads();

    for (int c = 0; c < NCH; c++) {
        const int cbuf = c & 1;
        float2 nxt;
        const bool pf = (tid < 128) && (c + 1 < NCH);
        if (pf) nxt = __ldg((const float2*)(sa_src + (c + 1) * 128 + tid));

        // ---- scan: fp32 state, fp16 tiles ----
        const float2* sab = sa_s + cbuf * 128;
#pragma unroll 4
        for (int tt = 0; tt < TC; tt++) {
            float2 sa = sab[tt * 4 + aidx];
            float s = sa.x, a = sa.y;
            q0 = omp0 * q0 + phi0 * s;
            q1 = omp1 * q1 + phi1 * s;
            h0 = omc0 * h0 + chi0 * a;
            h1 = omc1 * h1 + chi1 * a;
            int row = tt * 4 + aidx;
            Hs_h2[row * LDW + d2] = __floats2half2_rn(h0, h1);
            Qs_h2[row * LDW + d2] = __floats2half2_rn(q0, q1);
        }
        if (pf) sa_s[(cbuf ^ 1) * 128 + tid] = nxt;
        __syncthreads();   // tiles ready

        // ---- GEMM + epilogue, two passes over N halves ----
        float pl0[2] = {0.f, 0.f}, pl1[2] = {0.f, 0.f};
        float accx[2][4];
#pragma unroll
        for (int mt = 0; mt < 2; mt++)
#pragma unroll
            for (int i = 0; i < 4; i++) accx[mt][i] = 0.0f;

#pragma unroll
        for (int p = 0; p < 2; p++) {
            float acc[2][4][4];
#pragma unroll
            for (int mt = 0; mt < 2; mt++)
#pragma unroll
                for (int nt = 0; nt < 4; nt++)
#pragma unroll
                    for (int i = 0; i < 4; i++) acc[mt][nt][i] = 0.0f;

#pragma unroll
            for (int ks = 0; ks < 8; ks++) {
                unsigned bf0[4], bf1[4], bfx[2];
                ldsm4(bf0, bb[0] + p * (64 * LDB) + ks * 32);
                ldsm4(bf1, bb[1] + p * (64 * LDB) + ks * 32);
                if (p == 1 && nwp == 1) ldsm2(bfx, bbx + ks * 32);
#pragma unroll
                for (int mt = 0; mt < 2; mt++) {
                    unsigned af[4];
                    ldsm4(af, amt[mt] + ks * 32);
                    mma16816(acc[mt][0], af, bf0[0], bf0[1]);
                    mma16816(acc[mt][1], af, bf0[2], bf0[3]);
                    mma16816(acc[mt][2], af, bf1[0], bf1[1]);
                    mma16816(acc[mt][3], af, bf1[2], bf1[3]);
                    if (p == 1 && nwp == 1)
                        mma16816(accx[mt], af, bfx[0], bfx[1]);
                }
            }

            // epilogue for this pass: Q fragments via ldmatrix (acc layout)
#pragma unroll
            for (int nt = 0; nt < 4; nt++) {
                int col = p * 64 + nwp * 32 + nt * 8;
                float2 bet = make_float2(beta_s[col + 2 * tg], beta_s[col + 2 * tg + 1]);
                unsigned qf[4];
                ldsm4(qf, qbase + (unsigned)(col * 2));
#pragma unroll
                for (int mt = 0; mt < 2; mt++) {
                    float2 qv0 = __half22float2(*(__half2*)&qf[2 * mt]);
                    float2 qv1 = __half22float2(*(__half2*)&qf[2 * mt + 1]);
                    pl0[mt] += (acc[mt][nt][0] + bet.x) * qv0.x
                             + (acc[mt][nt][1] + bet.y) * qv0.y;
                    pl1[mt] += (acc[mt][nt][2] + bet.x) * qv1.x
                             + (acc[mt][nt][3] + bet.y) * qv1.y;
                }
            }
        }

        // kappa-term (col 128) lives in accx reg 0/2 of tg==0 threads
#pragma unroll
        for (int mt = 0; mt < 2; mt++) {
            if (nwp == 1 && tg == 0) {
                pl0[mt] += accx[mt][0];
                pl1[mt] += accx[mt][2];
            }
            pl0[mt] += __shfl_xor_sync(0xffffffffu, pl0[mt], 1);
            pl0[mt] += __shfl_xor_sync(0xffffffffu, pl0[mt], 2);
            pl1[mt] += __shfl_xor_sync(0xffffffffu, pl1[mt], 1);
            pl1[mt] += __shfl_xor_sync(0xffffffffu, pl1[mt], 2);
            if (tg == 0) {
                int r0 = mw * 32 + mt * 16 + g;
                lpart[nwp * 128 + r0]     = pl0[mt];
                lpart[nwp * 128 + r0 + 8] = pl1[mt];
            }
        }
        __syncthreads();   // lpart ready; also protects tiles & sa buffers

        if (tid < 128) {   // combine 2 n-group partials, store logits
            float lg = lpart[tid] + lpart[128 + tid];
            int tt = tid >> 2, a = tid & 3;
            out[((size_t)(c * TC + tt) * B_DIM + b) * A_DIM + a] = lg;
        }
    }

    // final q, h: shape (B, A, D)
    float* out_q = out + (size_t)NLOGIT;
    float* out_h = out_q + B_DIM * A_DIM * D_DIM;
    ((float2*)out_q)[(b * A_DIM + aidx) * 64 + d2] = make_float2(q0, q1);
    ((float2*)out_h)[(b * A_DIM + aidx) * 64 + d2] = make_float2(h0, h1);
}

extern "C" void kernel_launch(void* const* d_in, const int* in_sizes, int n_in,
                              void* d_out, int out_size) {
    const float* inp       = (const float*)d_in[0];
    const float* phi_raw   = (const float*)d_in[1];
    const float* chi_raw   = (const float*)d_in[2];
    const float* beta_raw  = (const float*)d_in[3];
    const float* kappa_raw = (const float*)d_in[4];
    const float* C_raw     = (const float*)d_in[5];
    float* out = (float*)d_out;

    cudaFuncSetAttribute(gql_main, cudaFuncAttributeMaxDynamicSharedMemorySize,
                         SMEM_BYTES);

    prep_kernel<<<(T_DIM * B_DIM + 255) / 256, 256>>>(inp);
    gql_main<<<B_DIM, 256, SMEM_BYTES>>>(inp, phi_raw, chi_raw, beta_raw,
                                         kappa_raw, C_raw, out);
}